// round 3
// baseline (speedup 1.0000x reference)
#include <cuda_runtime.h>
#include <cuda_bf16.h>

// SNN Leaky (snntorch, reset='subtract'), arithmetic FROZEN (bit-matches R1 pass):
//   reset = (mem > 1) ? 1 : 0
//   mem   = ((0.95*mem) + x) - reset   [strict __fmul_rn/__fadd_rn/__fsub_rn]
//   spk   = (mem > 1) ? 1 : 0
// Output flat [T, N], N = 3145728, T = 50. Pure HBM-write-bound (629 MB stream).
//
// R3 change: 256-bit stores (sm_100+ st.global.v8.f32, evict-first). One store
// instruction per thread per step = 8 floats; a warp writes 1024B contiguous in
// one wavefront. Halves L1tex store wavefronts + store instruction count vs
// STG.128 and doubles per-request burst size at DRAM.

#define SNN_THREADS 256
#define BETA 0.95f
#define THR  1.0f

__device__ __forceinline__ void snn_step(float& m, float xv, float& s)
{
    const float r = (m > THR) ? THR : 0.0f;
    m = __fsub_rn(__fadd_rn(__fmul_rn(BETA, m), xv), r);
    s = (m > THR) ? 1.0f : 0.0f;
}

__device__ __forceinline__ void st256_cs(float* p,
                                         float s0, float s1, float s2, float s3,
                                         float s4, float s5, float s6, float s7)
{
    asm volatile(
        "st.global.cs.v8.f32 [%0], {%1,%2,%3,%4,%5,%6,%7,%8};"
        :: "l"(p), "f"(s0), "f"(s1), "f"(s2), "f"(s3),
                   "f"(s4), "f"(s5), "f"(s6), "f"(s7)
        : "memory");
}

template <int NSTEPS>
__global__ __launch_bounds__(SNN_THREADS)
void snn_kernel_v3(const float4* __restrict__ x, float* __restrict__ out, int n)
{
    const int n8 = n >> 3;
    const int i = blockIdx.x * SNN_THREADS + threadIdx.x;   // one thread = 8 floats
    if (i >= n8) return;

    const float4 xa = x[2 * i];
    const float4 xb = x[2 * i + 1];

    float a0 = 0.f, a1 = 0.f, a2 = 0.f, a3 = 0.f;
    float b0 = 0.f, b1 = 0.f, b2 = 0.f, b3 = 0.f;

    float* obase = out + (size_t)i * 8;

#pragma unroll
    for (int t = 0; t < NSTEPS; ++t) {
        float sa0, sa1, sa2, sa3, sb0, sb1, sb2, sb3;
        snn_step(a0, xa.x, sa0);
        snn_step(a1, xa.y, sa1);
        snn_step(a2, xa.z, sa2);
        snn_step(a3, xa.w, sa3);
        snn_step(b0, xb.x, sb0);
        snn_step(b1, xb.y, sb1);
        snn_step(b2, xb.z, sb2);
        snn_step(b3, xb.w, sb3);

        st256_cs(obase + (size_t)t * n,
                 sa0, sa1, sa2, sa3, sb0, sb1, sb2, sb3);
    }
}

// Generic runtime step count: float4 path (R1 structure).
__global__ __launch_bounds__(SNN_THREADS)
void snn_kernel_gen4(const float4* __restrict__ x, float4* __restrict__ out,
                     int n4, int nsteps)
{
    int i = blockIdx.x * SNN_THREADS + threadIdx.x;
    if (i >= n4) return;

    const float4 xv = x[i];
    float m0 = 0.f, m1 = 0.f, m2 = 0.f, m3 = 0.f;
    float4* o = out + i;

    for (int t = 0; t < nsteps; ++t) {
        float4 s;
        snn_step(m0, xv.x, s.x);
        snn_step(m1, xv.y, s.y);
        snn_step(m2, xv.z, s.z);
        snn_step(m3, xv.w, s.w);
        __stcs(o + (size_t)t * n4, s);
    }
}

// Scalar tail for n % 8 != 0 (not hit for this shape).
__global__ __launch_bounds__(SNN_THREADS)
void snn_kernel_tail(const float* __restrict__ x, float* __restrict__ out,
                     int start, int n, int nsteps)
{
    int i = start + blockIdx.x * SNN_THREADS + threadIdx.x;
    if (i >= n) return;

    const float xv = x[i];
    float m = 0.0f;
    for (int t = 0; t < nsteps; ++t) {
        float s;
        snn_step(m, xv, s);
        out[(size_t)t * n + i] = s;
    }
}

extern "C" void kernel_launch(void* const* d_in, const int* in_sizes, int n_in,
                              void* d_out, int out_size)
{
    const float* x = (const float*)d_in[0];
    float* out = (float*)d_out;

    const int n = in_sizes[0];          // 3,145,728
    const int nsteps = out_size / n;    // 50

    if (nsteps == 50 && (n % 8) == 0) {
        const int n8 = n / 8;                                   // 393,216 threads
        const int grid = (n8 + SNN_THREADS - 1) / SNN_THREADS;  // 1536 blocks
        snn_kernel_v3<50><<<grid, SNN_THREADS>>>(
            (const float4*)x, out, n);
    } else {
        const int n4 = n / 4;
        const int tail = n - n4 * 4;
        if (n4 > 0) {
            const int grid = (n4 + SNN_THREADS - 1) / SNN_THREADS;
            snn_kernel_gen4<<<grid, SNN_THREADS>>>(
                (const float4*)x, (float4*)out, n4, nsteps);
        }
        if (tail > 0) {
            snn_kernel_tail<<<1, SNN_THREADS>>>(x, out, n4 * 4, n, nsteps);
        }
    }
}